// round 1
// baseline (speedup 1.0000x reference)
#include <cuda_runtime.h>
#include <math.h>

// Problem constants (fixed by setup_inputs; num_time_steps==8 always)
#define BN 8
#define XN 128
#define YN 128
#define YHN 65
#define WCH 24
#define DL 4
#define TSTEPS 8
#define NPAIR 12          // WCH/2
#define PTS (XN*YHN)      // 8320 spectral points
#define QN (BN*WCH)       // 192

// Scratch (module-scope device arrays; no runtime allocation)
__device__ float  d_h [BN*XN*YN*WCH];            // h: [b][x][y][c]
__device__ float2 d_Hy[BN*XN*YHN*WCH];           // after Y-rfft: [b][x][ky][c]
__device__ float2 d_Hf[PTS*QN];                  // after X-fft:  [p][b][c], p=kx*65+ky
__device__ float2 d_Yf[PTS*QN];                  // after spec:   [p][b][o]
__device__ float2 d_Gy[BN*XN*YHN*WCH];           // after inv-X:  [b][x][ky][o]

__device__ __forceinline__ float2 cplx_mul(float2 a, float2 b){
    return make_float2(a.x*b.x - a.y*b.y, a.x*b.y + a.y*b.x);
}

__device__ __forceinline__ void fill_tw(float2* tw, int tid, int nthr){
    for (int k = tid; k < 64; k += nthr){
        float ang = -6.2831853071795864769f * (float)k / 128.f;
        float s, c; sincosf(ang, &s, &c);
        tw[k] = make_float2(c, s);
    }
}

// In-place radix-2 DIT FFT of 128 complex points in shared memory, one warp.
// tw[k] = exp(-2*pi*i*k/128), k=0..63. inv: conjugate twiddles (no scaling).
__device__ __forceinline__ void fft128(float2* a, const float2* tw, int lane, bool inv){
    // bit reversal (7 bits)
    #pragma unroll
    for (int e = 0; e < 4; e++){
        int i = lane + 32*e;
        int j = __brev(i) >> 25;
        if (j > i){ float2 t = a[i]; a[i] = a[j]; a[j] = t; }
    }
    __syncwarp();
    #pragma unroll
    for (int s = 1; s <= 7; s++){
        int half = 1 << (s-1);
        #pragma unroll
        for (int r = 0; r < 2; r++){
            int t   = lane + 32*r;
            int j   = t & (half-1);
            int i1  = ((t >> (s-1)) << s) + j;
            int i2  = i1 + half;
            float2 w = tw[j << (7-s)];
            if (inv) w.y = -w.y;
            float2 u = a[i1];
            float2 v = cplx_mul(a[i2], w);
            a[i1] = make_float2(u.x+v.x, u.y+v.y);
            a[i2] = make_float2(u.x-v.x, u.y-v.y);
        }
        __syncwarp();
    }
}

// ---------------- h0 = x @ in_w + in_b -------------------------------------
__global__ __launch_bounds__(256) void k_init(const float* __restrict__ x,
                                              const float* __restrict__ inw,
                                              const float* __restrict__ inb){
    int idx = blockIdx.x*256 + threadIdx.x;
    if (idx >= BN*XN*YN*WCH) return;
    int c = idx % WCH, pix = idx / WCH;
    d_h[idx] = inb[c] + x[pix*2+0]*inw[c] + x[pix*2+1]*inw[WCH + c];
}

// ---------------- stage 1: rFFT along Y (channel pairs packed) -------------
__global__ __launch_bounds__(384) void k_ffty(){
    __shared__ float2 tw[64];
    __shared__ float2 buf[NPAIR*129];
    __shared__ float2 stg[YHN*WCH];       // 1560 float2
    int tid = threadIdx.x;
    int bx  = blockIdx.x;                 // b*128 + x
    fill_tw(tw, tid, 384);
    const float* hp = d_h + (size_t)bx*YN*WCH;
    for (int idx = tid; idx < YN*WCH; idx += 384){
        int y = idx / WCH, c = idx % WCH;
        ((float*)buf)[((c>>1)*129 + y)*2 + (c&1)] = hp[idx];
    }
    __syncthreads();
    int w = tid >> 5, lane = tid & 31;
    float2* line = buf + w*129;
    fft128(line, tw, lane, false);
    // unpack packed pair (c0 + i*c1) into two rfft spectra
    for (int ky = lane; ky <= 64; ky += 32){
        float2 zk = line[ky];
        float2 zm = line[(128-ky) & 127];
        float2 c0 = make_float2(0.5f*(zk.x+zm.x), 0.5f*(zk.y-zm.y));
        float2 c1 = make_float2(0.5f*(zk.y+zm.y), 0.5f*(zm.x-zk.x));
        stg[ky*WCH + 2*w    ] = c0;
        stg[ky*WCH + 2*w + 1] = c1;
    }
    __syncthreads();
    float2* outp = d_Hy + (size_t)bx*YHN*WCH;
    for (int idx = tid; idx < YHN*WCH; idx += 384) outp[idx] = stg[idx];
}

// ---------------- stage 2: complex FFT along X -----------------------------
__global__ __launch_bounds__(768) void k_fftx(){
    __shared__ float2 tw[64];
    __shared__ float2 buf[WCH*129];
    int tid = threadIdx.x;
    int b = blockIdx.x / YHN, ky = blockIdx.x % YHN;
    fill_tw(tw, tid, 768);
    for (int idx = tid; idx < XN*WCH; idx += 768){
        int x = idx / WCH, c = idx % WCH;
        buf[c*129 + x] = d_Hy[(size_t)((b*XN + x)*YHN + ky)*WCH + c];
    }
    __syncthreads();
    int w = tid >> 5, lane = tid & 31;
    fft128(buf + w*129, tw, lane, false);
    __syncthreads();
    for (int idx = tid; idx < XN*WCH; idx += 768){
        int kx = idx / WCH, c = idx % WCH;
        d_Hf[(size_t)(kx*YHN + ky)*QN + b*WCH + c] = buf[c*129 + kx];
    }
}

// ---------------- stage 3: per-point complex channel mix -------------------
// Yf[p][b][o] = sum_i Hf[p][b][i] * Wc[i][o][p]
__device__ __forceinline__ int hsw(int q, int t){ return q*32 + ((t + q) & 31); }

__global__ __launch_bounds__(256) void k_spec(const float* __restrict__ specw_f, int d){
    __shared__ float2 Hs[QN*32];   // 48KB, swizzled [q][t]
    int tid = threadIdx.x;
    int p0 = blockIdx.x * 32;
    const float2* specw = (const float2*)specw_f;
    for (int idx = tid; idx < 32*QN; idx += 256){
        int t = idx / QN, q = idx % QN;
        Hs[hsw(q, t)] = d_Hf[(size_t)(p0 + t)*QN + q];
    }
    __syncthreads();
    int w = tid >> 5, lane = tid & 31;   // lane <-> spectral point p0+lane
    float2 acc[3][8];
    #pragma unroll
    for (int j = 0; j < 3; j++)
        #pragma unroll
        for (int b = 0; b < 8; b++) acc[j][b] = make_float2(0.f, 0.f);
    for (int i = 0; i < WCH; i++){
        float2 hv[8];
        #pragma unroll
        for (int b = 0; b < 8; b++) hv[b] = Hs[hsw(b*WCH + i, lane)];
        #pragma unroll
        for (int j = 0; j < 3; j++){
            int o = w + 8*j;
            float2 wv = specw[(size_t)(d*576 + i*WCH + o)*PTS + p0 + lane];
            #pragma unroll
            for (int b = 0; b < 8; b++){
                acc[j][b].x = fmaf( hv[b].x, wv.x, acc[j][b].x);
                acc[j][b].x = fmaf(-hv[b].y, wv.y, acc[j][b].x);
                acc[j][b].y = fmaf( hv[b].x, wv.y, acc[j][b].y);
                acc[j][b].y = fmaf( hv[b].y, wv.x, acc[j][b].y);
            }
        }
    }
    __syncthreads();
    #pragma unroll
    for (int j = 0; j < 3; j++){
        int o = w + 8*j;
        #pragma unroll
        for (int b = 0; b < 8; b++) Hs[hsw(b*WCH + o, lane)] = acc[j][b];
    }
    __syncthreads();
    for (int idx = tid; idx < 32*QN; idx += 256){
        int t = idx / QN, q = idx % QN;
        d_Yf[(size_t)(p0 + t)*QN + q] = Hs[hsw(q, t)];
    }
}

// ---------------- stage 4: inverse complex FFT along X (x 1/128) -----------
__global__ __launch_bounds__(768) void k_ifftx(){
    __shared__ float2 tw[64];
    __shared__ float2 buf[WCH*129];
    int tid = threadIdx.x;
    int b = blockIdx.x / YHN, ky = blockIdx.x % YHN;
    fill_tw(tw, tid, 768);
    for (int idx = tid; idx < XN*WCH; idx += 768){
        int kx = idx / WCH, o = idx % WCH;
        buf[o*129 + kx] = d_Yf[(size_t)(kx*YHN + ky)*QN + b*WCH + o];
    }
    __syncthreads();
    int w = tid >> 5, lane = tid & 31;
    fft128(buf + w*129, tw, lane, true);
    __syncthreads();
    const float sc = 1.f/128.f;
    for (int idx = tid; idx < XN*WCH; idx += 768){
        int x = idx / WCH, o = idx % WCH;
        float2 v = buf[o*129 + x];
        d_Gy[(size_t)((b*XN + x)*YHN + ky)*WCH + o] = make_float2(v.x*sc, v.y*sc);
    }
}

// ---------------- stage 5: inverse rFFT along Y + 1x1 conv + relu + out ----
__global__ __launch_bounds__(384) void k_ifftyconv(const float* __restrict__ convw,
                                                   const float* __restrict__ convb,
                                                   const float* __restrict__ outw,
                                                   const float* __restrict__ outb,
                                                   float* __restrict__ out,
                                                   int d, int t, int last){
    __shared__ float2 tw[64];
    __shared__ float2 buf[NPAIR*129];
    __shared__ float2 stg[YHN*WCH];    // reused as hnew (3072 floats fit in 3120 f2)
    __shared__ float  hs[YN*WCH];
    __shared__ float  cw[WCH*WCH];
    __shared__ float  cb[WCH];
    __shared__ float  ow[WCH];
    __shared__ float  ob;
    int tid = threadIdx.x;
    int bx  = blockIdx.x;              // b*128 + x
    int b   = bx >> 7, x = bx & 127;
    fill_tw(tw, tid, 384);
    const float2* gy = d_Gy + (size_t)bx*YHN*WCH;
    for (int idx = tid; idx < YHN*WCH; idx += 384) stg[idx] = gy[idx];
    float* hp = d_h + (size_t)bx*YN*WCH;
    for (int idx = tid; idx < YN*WCH; idx += 384) hs[idx] = hp[idx];
    for (int idx = tid; idx < WCH*WCH; idx += 384) cw[idx] = convw[d*WCH*WCH + idx];
    if (tid < WCH){ cb[tid] = convb[d*WCH + tid]; ow[tid] = outw[tid]; }
    if (tid == 0) ob = outb[0];
    __syncthreads();

    int w = tid >> 5, lane = tid & 31;
    float2* line = buf + w*129;
    int o0 = 2*w, o1 = 2*w + 1;
    // Build full-length packed spectrum: S = mirror(G_o0) + i*mirror(G_o1),
    // with Im of DC/Nyquist discarded (matches irfft semantics exactly).
    for (int k = lane; k < 128; k += 32){
        float2 z;
        if (k <= 64){
            float2 g0 = stg[k*WCH + o0];
            float2 g1 = stg[k*WCH + o1];
            if (k == 0 || k == 64){ g0.y = 0.f; g1.y = 0.f; }
            z = make_float2(g0.x - g1.y, g0.y + g1.x);
        } else {
            int km = 128 - k;
            float2 g0 = stg[km*WCH + o0];
            float2 g1 = stg[km*WCH + o1];
            z = make_float2(g0.x + g1.y, g1.x - g0.y);
        }
        line[k] = z;
    }
    __syncwarp();
    fft128(line, tw, lane, true);      // inverse; scale 1/128 folded below
    __syncthreads();                   // stg now reusable as hnew

    float* hnew = (float*)stg;
    const float sc = 1.f/128.f;
    for (int idx = tid; idx < YN*WCH; idx += 384){
        int y = idx / WCH, o = idx % WCH;
        float acc = cb[o];
        #pragma unroll
        for (int i = 0; i < WCH; i++) acc = fmaf(hs[y*WCH + i], cw[i*WCH + o], acc);
        float2 v  = buf[(o>>1)*129 + y];
        float  x1 = ((o & 1) ? v.y : v.x) * sc;
        hnew[idx] = fmaxf(x1, 0.f) + acc;
    }
    __syncthreads();
    for (int idx = tid; idx < YN*WCH; idx += 384) hp[idx] = hnew[idx];
    if (last){
        for (int y = tid; y < YN; y += 384){
            float acc = ob;
            #pragma unroll
            for (int c = 0; c < WCH; c++) acc = fmaf(hnew[y*WCH + c], ow[c], acc);
            out[(((size_t)b*TSTEPS + t)*XN + x)*YN + y] = acc;
        }
    }
}

// ---------------------------------------------------------------------------
extern "C" void kernel_launch(void* const* d_in, const int* in_sizes, int n_in,
                              void* d_out, int out_size){
    (void)in_sizes; (void)n_in; (void)out_size;
    const float* x     = (const float*)d_in[0];
    const float* in_w  = (const float*)d_in[1];
    const float* in_b  = (const float*)d_in[2];
    const float* specw = (const float*)d_in[3];
    const float* convw = (const float*)d_in[4];
    const float* convb = (const float*)d_in[5];
    const float* outw  = (const float*)d_in[6];
    const float* outb  = (const float*)d_in[7];
    float* out = (float*)d_out;

    int npix = BN*XN*YN*WCH;
    k_init<<<(npix + 255)/256, 256>>>(x, in_w, in_b);
    for (int t = 0; t < TSTEPS; t++){
        for (int d = 0; d < DL; d++){
            k_ffty     <<<BN*XN , 384>>>();
            k_fftx     <<<BN*YHN, 768>>>();
            k_spec     <<<PTS/32, 256>>>(specw, d);
            k_ifftx    <<<BN*YHN, 768>>>();
            k_ifftyconv<<<BN*XN , 384>>>(convw, convb, outw, outb, out, d, t, d == DL-1);
        }
    }
}